// round 2
// baseline (speedup 1.0000x reference)
#include <cuda_runtime.h>
#include <cuda_bf16.h>
#include <math.h>

// Problem constants
#define B_   2
#define S_   2048
#define DIM_ 2048
#define NH_  32
#define NKV_ 8
#define HD_  64
#define QKVO 3072          // (32 + 2*8) * 64
#define QOFF 2048          // q end
#define KOFF 2048          // k start within row
#define VOFF 2560          // v start within row
#define EPS_ 1e-5f

// Scratch (device globals — no allocation allowed)
__device__ float g_qkv[(size_t)B_ * S_ * QKVO];   // 50.3 MB
__device__ float g_attn[(size_t)B_ * S_ * DIM_];  // 33.5 MB

// ---------------------------------------------------------------------------
// GEMM: C[M,N] = A[M,K] * B, where B is either NK (BT=true, row n contiguous
// in k) or KN (BT=false). Tile 128x64, BK=16, 256 threads, 4x8 per thread.
// ---------------------------------------------------------------------------
template <bool BT>
__global__ __launch_bounds__(256) void gemm_kernel(
    const float* __restrict__ A, const float* __restrict__ Bm,
    float* __restrict__ C, int M, int N, int K)
{
    __shared__ float As[16][128];
    __shared__ float Bs[16][64];

    const int tid = threadIdx.x;
    const int ty = tid >> 3;        // 0..31
    const int tx = tid & 7;         // 0..7
    const int row0 = blockIdx.y * 128 + ty * 4;
    const int col0 = blockIdx.x * 64 + tx * 8;

    float acc[4][8];
#pragma unroll
    for (int i = 0; i < 4; i++)
#pragma unroll
        for (int j = 0; j < 8; j++) acc[i][j] = 0.f;

    for (int k0 = 0; k0 < K; k0 += 16) {
        // A tile: 128x16
#pragma unroll
        for (int i = 0; i < 8; i++) {
            int e = tid + i * 256;
            int m = e >> 4, k = e & 15;
            As[k][m] = A[(size_t)(blockIdx.y * 128 + m) * K + k0 + k];
        }
        // B tile: 64x16 (BT) or 16x64 (!BT)
#pragma unroll
        for (int i = 0; i < 4; i++) {
            int e = tid + i * 256;
            if (BT) {
                int n = e >> 4, k = e & 15;
                Bs[k][n] = Bm[(size_t)(blockIdx.x * 64 + n) * K + k0 + k];
            } else {
                int k = e >> 6, n = e & 63;
                Bs[k][n] = Bm[(size_t)(k0 + k) * N + blockIdx.x * 64 + n];
            }
        }
        __syncthreads();
#pragma unroll
        for (int kk = 0; kk < 16; kk++) {
            float a[4], b[8];
#pragma unroll
            for (int i = 0; i < 4; i++) a[i] = As[kk][ty * 4 + i];
#pragma unroll
            for (int j = 0; j < 8; j++) b[j] = Bs[kk][tx * 8 + j];
#pragma unroll
            for (int i = 0; i < 4; i++)
#pragma unroll
                for (int j = 0; j < 8; j++) acc[i][j] += a[i] * b[j];
        }
        __syncthreads();
    }
#pragma unroll
    for (int i = 0; i < 4; i++)
#pragma unroll
        for (int j = 0; j < 8; j++)
            C[(size_t)(row0 + i) * N + col0 + j] = acc[i][j];
}

// ---------------------------------------------------------------------------
// Fused LayerNorm + RoPE, in-place on g_qkv. One warp per (b,s,head),
// heads 0..31 = Q, 32..39 = K. Lane j owns the rotary pair (2j, 2j+1).
// ---------------------------------------------------------------------------
__global__ __launch_bounds__(128) void lnrope_kernel(
    const float* __restrict__ qg, const float* __restrict__ qb,
    const float* __restrict__ kg, const float* __restrict__ kb,
    const float* __restrict__ fcos, const float* __restrict__ fsin)
{
    int gw = blockIdx.x * 4 + (threadIdx.x >> 5);
    int lane = threadIdx.x & 31;
    int h = gw % 40;
    int bs = gw / 40;              // 0 .. B*S-1
    int s = bs & (S_ - 1);

    float* ptr;
    const float* g;
    const float* be;
    size_t rowbase = (size_t)bs * QKVO;
    if (h < 32) { ptr = g_qkv + rowbase + h * 64;               g = qg; be = qb; }
    else        { ptr = g_qkv + rowbase + KOFF + (h - 32) * 64; g = kg; be = kb; }

    float2 v = reinterpret_cast<float2*>(ptr)[lane];
    float sum = v.x + v.y;
    float sq  = v.x * v.x + v.y * v.y;
#pragma unroll
    for (int off = 16; off > 0; off >>= 1) {
        sum += __shfl_xor_sync(0xffffffffu, sum, off);
        sq  += __shfl_xor_sync(0xffffffffu, sq,  off);
    }
    float mu   = sum * (1.f / 64.f);
    float var  = sq * (1.f / 64.f) - mu * mu;
    float rstd = rsqrtf(var + EPS_);

    float xr = (v.x - mu) * rstd * g[2 * lane]     + be[2 * lane];
    float xi = (v.y - mu) * rstd * g[2 * lane + 1] + be[2 * lane + 1];

    float c  = fcos[s * 32 + lane];
    float sn = fsin[s * 32 + lane];
    float2 o;
    o.x = xr * c - xi * sn;
    o.y = xr * sn + xi * c;
    reinterpret_cast<float2*>(ptr)[lane] = o;
}

// ---------------------------------------------------------------------------
// Flash attention (fp32 SIMT). Block = 128 threads, one 64-row Q tile of one
// (b,h). Online softmax over causal K tiles. Smem layouts are transposed
// (Qt[d][r], Kt[d][c], Pt[c][r], Vs[kk][d]) with stride 65 for bank safety.
// ---------------------------------------------------------------------------
__global__ __launch_bounds__(128) void attn_kernel()
{
    extern __shared__ float sm[];
    float* Qt = sm;                 // [64][65]  Qt[d*65 + r]
    float* Kt = sm + 64 * 65;       // [64][65]  Kt[d*65 + c]
    float* Vs = sm + 2 * 64 * 65;   // [64][65]  Vs[kk*65 + d]
    float* Pt = sm + 3 * 64 * 65;   // [64][65]  Pt[c*65 + r]

    const int tid = threadIdx.x;
    const int ty = tid >> 3;        // 0..15 -> rows ty*4..+3
    const int tx = tid & 7;         // 0..7  -> cols tx*8..+7
    const int b = blockIdx.z, h = blockIdx.y, qb = blockIdx.x;
    const int kvh = h >> 2;
    const float scale = 0.125f;     // 1/sqrt(64)

    const float* qbase = g_qkv + ((size_t)(b * S_ + qb * 64)) * QKVO + h * 64;
#pragma unroll
    for (int i = 0; i < 32; i++) {
        int e = tid + i * 128;
        int r = e >> 6, d = e & 63;
        Qt[d * 65 + r] = qbase[(size_t)r * QKVO + d] * scale;
    }

    float m_i[4], l_i[4], acc[4][8];
#pragma unroll
    for (int i = 0; i < 4; i++) { m_i[i] = -3e38f; l_i[i] = 0.f; }
#pragma unroll
    for (int i = 0; i < 4; i++)
#pragma unroll
        for (int j = 0; j < 8; j++) acc[i][j] = 0.f;

    for (int kb = 0; kb <= qb; kb++) {
        __syncthreads();  // prior-iter smem reads done (also covers Q load)
        const float* kbase = g_qkv + ((size_t)(b * S_ + kb * 64)) * QKVO + KOFF + kvh * 64;
        const float* vbase = g_qkv + ((size_t)(b * S_ + kb * 64)) * QKVO + VOFF + kvh * 64;
#pragma unroll
        for (int i = 0; i < 32; i++) {
            int e = tid + i * 128;
            int kk = e >> 6, d = e & 63;
            Kt[d * 65 + kk] = kbase[(size_t)kk * QKVO + d];
            Vs[kk * 65 + d] = vbase[(size_t)kk * QKVO + d];
        }
        __syncthreads();

        // S = Q K^T  (scaled)
        float s[4][8];
#pragma unroll
        for (int i = 0; i < 4; i++)
#pragma unroll
            for (int j = 0; j < 8; j++) s[i][j] = 0.f;
#pragma unroll 4
        for (int d = 0; d < 64; d++) {
            float qv[4], kv[8];
#pragma unroll
            for (int i = 0; i < 4; i++) qv[i] = Qt[d * 65 + ty * 4 + i];
#pragma unroll
            for (int j = 0; j < 8; j++) kv[j] = Kt[d * 65 + tx * 8 + j];
#pragma unroll
            for (int i = 0; i < 4; i++)
#pragma unroll
                for (int j = 0; j < 8; j++) s[i][j] += qv[i] * kv[j];
        }
        if (kb == qb) {
#pragma unroll
            for (int i = 0; i < 4; i++)
#pragma unroll
                for (int j = 0; j < 8; j++)
                    if (tx * 8 + j > ty * 4 + i) s[i][j] = -3e38f;
        }

        // online softmax per row
#pragma unroll
        for (int i = 0; i < 4; i++) {
            float mt = s[i][0];
#pragma unroll
            for (int j = 1; j < 8; j++) mt = fmaxf(mt, s[i][j]);
#pragma unroll
            for (int off = 4; off > 0; off >>= 1)
                mt = fmaxf(mt, __shfl_xor_sync(0xffffffffu, mt, off));
            float mn = fmaxf(m_i[i], mt);
            float corr = __expf(m_i[i] - mn);
            float rs = 0.f;
#pragma unroll
            for (int j = 0; j < 8; j++) {
                float p = __expf(s[i][j] - mn);
                s[i][j] = p;
                rs += p;
            }
#pragma unroll
            for (int off = 4; off > 0; off >>= 1)
                rs += __shfl_xor_sync(0xffffffffu, rs, off);
            l_i[i] = l_i[i] * corr + rs;
            m_i[i] = mn;
#pragma unroll
            for (int j = 0; j < 8; j++) acc[i][j] *= corr;
        }

        // stage P
#pragma unroll
        for (int i = 0; i < 4; i++)
#pragma unroll
            for (int j = 0; j < 8; j++)
                Pt[(tx * 8 + j) * 65 + ty * 4 + i] = s[i][j];
        __syncthreads();

        // acc += P V
#pragma unroll 4
        for (int kk = 0; kk < 64; kk++) {
            float pv[4], vv[8];
#pragma unroll
            for (int i = 0; i < 4; i++) pv[i] = Pt[kk * 65 + ty * 4 + i];
#pragma unroll
            for (int j = 0; j < 8; j++) vv[j] = Vs[kk * 65 + tx * 8 + j];
#pragma unroll
            for (int i = 0; i < 4; i++)
#pragma unroll
                for (int j = 0; j < 8; j++) acc[i][j] += pv[i] * vv[j];
        }
    }

    float* obase = g_attn + ((size_t)(b * S_ + qb * 64)) * DIM_ + h * 64;
#pragma unroll
    for (int i = 0; i < 4; i++) {
        float inv = 1.f / l_i[i];
#pragma unroll
        for (int j = 0; j < 8; j++)
            obase[(size_t)(ty * 4 + i) * DIM_ + tx * 8 + j] = acc[i][j] * inv;
    }
}

// ---------------------------------------------------------------------------
extern "C" void kernel_launch(void* const* d_in, const int* in_sizes, int n_in,
                              void* d_out, int out_size)
{
    const float* x     = (const float*)d_in[0];
    const float* wqkv  = (const float*)d_in[1];
    const float* wo    = (const float*)d_in[2];
    const float* q_g   = (const float*)d_in[3];
    const float* q_b   = (const float*)d_in[4];
    const float* k_g   = (const float*)d_in[5];
    const float* k_b   = (const float*)d_in[6];
    const float* fcos  = (const float*)d_in[7];
    const float* fsin  = (const float*)d_in[8];
    // d_in[9] = mask (unused; causal mask applied analytically)
    float* out = (float*)d_out;

    float* qkv_p = nullptr;
    float* attn_p = nullptr;
    cudaGetSymbolAddress((void**)&qkv_p, g_qkv);
    cudaGetSymbolAddress((void**)&attn_p, g_attn);

    const int M = B_ * S_;  // 4096

    // 1) QKV projection: x (M x 2048) * wqkv^T (2048 x 3072)
    {
        dim3 grid(QKVO / 64, M / 128);
        gemm_kernel<true><<<grid, 256>>>(x, wqkv, qkv_p, M, QKVO, DIM_);
    }

    // 2) LayerNorm + RoPE in-place (40 heads per token, warp each)
    {
        int total_warps = B_ * S_ * 40;
        lnrope_kernel<<<total_warps / 4, 128>>>(q_g, q_b, k_g, k_b, fcos, fsin);
    }

    // 3) Flash attention
    {
        int smem = 4 * 64 * 65 * (int)sizeof(float);  // 66560 B
        cudaFuncSetAttribute(attn_kernel,
                             cudaFuncAttributeMaxDynamicSharedMemorySize, smem);
        dim3 grid(S_ / 64, NH_, B_);
        attn_kernel<<<grid, 128, smem>>>();
    }

    // 4) Output projection: attn (M x 2048) * wo (2048 x 2048, f-major)
    {
        dim3 grid(DIM_ / 64, M / 128);
        gemm_kernel<false><<<grid, 256>>>(attn_p, wo, out, M, DIM_, DIM_);
    }
}

// round 4
// speedup vs baseline: 3.2735x; 3.2735x over previous
#include <cuda_runtime.h>
#include <cuda_bf16.h>
#include <math.h>

// Problem constants
#define B_   2
#define S_   2048
#define DIM_ 2048
#define NH_  32
#define QKVO 3072          // (32 + 2*8) * 64
#define KOFF 2048          // k start within row
#define VOFF 2560          // v start within row
#define EPS_ 1e-5f

// Scratch (device globals — no allocation allowed)
__device__ float g_qkv[(size_t)B_ * S_ * QKVO];   // 50.3 MB
__device__ float g_attn[(size_t)B_ * S_ * DIM_];  // 33.5 MB

// ---------------------------------------------------------------------------
// GEMM: C[M,N] = A[M,K] * B.  BT=true: B is [N,K] row-major (NT gemm).
// BT=false: B is [K,N] row-major (NN gemm).
// Tile 128x128, BK=8, 256 threads, 8x8 per thread, double-buffered smem.
// ---------------------------------------------------------------------------
template <bool BT>
__global__ __launch_bounds__(256) void gemm_kernel(
    const float* __restrict__ A, const float* __restrict__ Bm,
    float* __restrict__ C, int M, int N, int K)
{
    __shared__ float As[2][8][128];
    __shared__ float Bs[2][8][128];

    const int tid = threadIdx.x;
    const int tx = tid & 15;            // 0..15  (cols)
    const int ty = tid >> 4;            // 0..15  (rows)
    const int row0 = ty * 8;
    const int col0 = tx * 8;
    const int bm = blockIdx.y * 128;
    const int bn = blockIdx.x * 128;

    // A load: one float4 per thread per k-tile (transposed store)
    const int a_row = tid >> 1;             // 0..127
    const int a_col = (tid & 1) * 4;        // 0 or 4
    const float* Ap = A + (size_t)(bm + a_row) * K + a_col;

    // B load: one float4 per thread per k-tile
    int b_row, b_col;
    const float* Bp;
    if (BT) { b_row = tid >> 1; b_col = (tid & 1) * 4;
              Bp = Bm + (size_t)(bn + b_row) * K + b_col; }
    else    { b_row = tid >> 5; b_col = (tid & 31) * 4;
              Bp = Bm + (size_t)b_row * N + bn + b_col; }

    float acc[8][8];
#pragma unroll
    for (int i = 0; i < 8; i++)
#pragma unroll
        for (int j = 0; j < 8; j++) acc[i][j] = 0.f;

    // prologue: tile 0 into buffer 0
    {
        float4 av = *(const float4*)Ap;
        float4 bv = *(const float4*)Bp;
        As[0][a_col + 0][a_row] = av.x;
        As[0][a_col + 1][a_row] = av.y;
        As[0][a_col + 2][a_row] = av.z;
        As[0][a_col + 3][a_row] = av.w;
        if (BT) {
            Bs[0][b_col + 0][b_row] = bv.x;
            Bs[0][b_col + 1][b_row] = bv.y;
            Bs[0][b_col + 2][b_row] = bv.z;
            Bs[0][b_col + 3][b_row] = bv.w;
        } else {
            *(float4*)&Bs[0][b_row][b_col] = bv;
        }
    }

    const int nk = K >> 3;
    for (int kt = 0; kt < nk; kt++) {
        const int buf = kt & 1;
        float4 av, bv;
        const bool pf = (kt + 1 < nk);
        if (pf) {
            av = *(const float4*)(Ap + (kt + 1) * 8);
            bv = BT ? *(const float4*)(Bp + (kt + 1) * 8)
                    : *(const float4*)(Bp + (size_t)(kt + 1) * 8 * N);
        }
        __syncthreads();

#pragma unroll
        for (int kk = 0; kk < 8; kk++) {
            float4 a0 = *(const float4*)&As[buf][kk][row0];
            float4 a1 = *(const float4*)&As[buf][kk][row0 + 4];
            float4 b0 = *(const float4*)&Bs[buf][kk][col0];
            float4 b1 = *(const float4*)&Bs[buf][kk][col0 + 4];
            float ar[8] = {a0.x, a0.y, a0.z, a0.w, a1.x, a1.y, a1.z, a1.w};
            float br[8] = {b0.x, b0.y, b0.z, b0.w, b1.x, b1.y, b1.z, b1.w};
#pragma unroll
            for (int i = 0; i < 8; i++)
#pragma unroll
                for (int j = 0; j < 8; j++) acc[i][j] += ar[i] * br[j];
        }

        if (pf) {
            const int nb = buf ^ 1;
            As[nb][a_col + 0][a_row] = av.x;
            As[nb][a_col + 1][a_row] = av.y;
            As[nb][a_col + 2][a_row] = av.z;
            As[nb][a_col + 3][a_row] = av.w;
            if (BT) {
                Bs[nb][b_col + 0][b_row] = bv.x;
                Bs[nb][b_col + 1][b_row] = bv.y;
                Bs[nb][b_col + 2][b_row] = bv.z;
                Bs[nb][b_col + 3][b_row] = bv.w;
            } else {
                *(float4*)&Bs[nb][b_row][b_col] = bv;
            }
        }
    }

#pragma unroll
    for (int i = 0; i < 8; i++) {
        float4 c0 = make_float4(acc[i][0], acc[i][1], acc[i][2], acc[i][3]);
        float4 c1 = make_float4(acc[i][4], acc[i][5], acc[i][6], acc[i][7]);
        float* crow = C + (size_t)(bm + row0 + i) * N + bn + col0;
        *(float4*)crow = c0;
        *(float4*)(crow + 4) = c1;
    }
}

// ---------------------------------------------------------------------------
// Fused LayerNorm + RoPE, in-place on g_qkv. One warp per (b,s,head),
// heads 0..31 = Q, 32..39 = K.
// ---------------------------------------------------------------------------
__global__ __launch_bounds__(128) void lnrope_kernel(
    const float* __restrict__ qg, const float* __restrict__ qb,
    const float* __restrict__ kg, const float* __restrict__ kb,
    const float* __restrict__ fcos, const float* __restrict__ fsin)
{
    int gw = blockIdx.x * 4 + (threadIdx.x >> 5);
    int lane = threadIdx.x & 31;
    int h = gw % 40;
    int bs = gw / 40;
    int s = bs & (S_ - 1);

    float* ptr;
    const float* g;
    const float* be;
    size_t rowbase = (size_t)bs * QKVO;
    if (h < 32) { ptr = g_qkv + rowbase + h * 64;               g = qg; be = qb; }
    else        { ptr = g_qkv + rowbase + KOFF + (h - 32) * 64; g = kg; be = kb; }

    float2 v = reinterpret_cast<float2*>(ptr)[lane];
    float sum = v.x + v.y;
    float sq  = v.x * v.x + v.y * v.y;
#pragma unroll
    for (int off = 16; off > 0; off >>= 1) {
        sum += __shfl_xor_sync(0xffffffffu, sum, off);
        sq  += __shfl_xor_sync(0xffffffffu, sq,  off);
    }
    float mu   = sum * (1.f / 64.f);
    float var  = sq * (1.f / 64.f) - mu * mu;
    float rstd = rsqrtf(var + EPS_);

    float xr = (v.x - mu) * rstd * g[2 * lane]     + be[2 * lane];
    float xi = (v.y - mu) * rstd * g[2 * lane + 1] + be[2 * lane + 1];

    float c  = fcos[s * 32 + lane];
    float sn = fsin[s * 32 + lane];
    float2 o;
    o.x = xr * c - xi * sn;
    o.y = xr * sn + xi * c;
    reinterpret_cast<float2*>(ptr)[lane] = o;
}

// ---------------------------------------------------------------------------
// Flash attention (fp32 SIMT v2). 128 threads, Q tile = 128 rows, K tile = 64.
// 8x8 micro-tile per thread (thread grid 16 rows x 8 cols).
// Smem: Qt[d][r] (pitch 128), Kt[d][c] (64), Vs[c][d] (64), Pt[c][r] (129).
// ---------------------------------------------------------------------------
#define AT_SMEM ((64 * 128 + 64 * 64 + 64 * 64 + 64 * 129) * 4)

__global__ __launch_bounds__(128) void attn_kernel()
{
    extern __shared__ float sm[];
    float* Qt = sm;                       // [64][128]
    float* Kt = sm + 64 * 128;            // [64][64]
    float* Vs = Kt + 64 * 64;             // [64][64]
    float* Pt = Vs + 64 * 64;             // [64][129]

    const int tid = threadIdx.x;
    const int ty = tid >> 3;              // 0..15 -> rows ty*8..+7
    const int tx = tid & 7;               // 0..7  -> cols tx*8..+7
    const int row0 = ty * 8;
    const int col0 = tx * 8;
    const int b = blockIdx.z, h = blockIdx.y;
    const int qb = (int)gridDim.x - 1 - (int)blockIdx.x;   // heavy tiles first
    const int kvh = h >> 2;
    const float scale = 0.125f;           // 1/sqrt(64)

    // Load + transpose Q (scaled): 128 rows x 64 d
    const float* qbase = g_qkv + ((size_t)(b * S_ + qb * 128)) * QKVO + h * 64;
#pragma unroll
    for (int i = 0; i < 16; i++) {
        int e = tid + i * 128;
        int r = e >> 4, d4 = (e & 15) * 4;
        float4 v = *(const float4*)(qbase + (size_t)r * QKVO + d4);
        Qt[(d4 + 0) * 128 + r] = v.x * scale;
        Qt[(d4 + 1) * 128 + r] = v.y * scale;
        Qt[(d4 + 2) * 128 + r] = v.z * scale;
        Qt[(d4 + 3) * 128 + r] = v.w * scale;
    }

    float m_i[8], l_i[8], acc[8][8];
#pragma unroll
    for (int i = 0; i < 8; i++) { m_i[i] = -1e30f; l_i[i] = 0.f; }
#pragma unroll
    for (int i = 0; i < 8; i++)
#pragma unroll
        for (int j = 0; j < 8; j++) acc[i][j] = 0.f;

    const int nkb = 2 * qb + 2;           // k tiles 0 .. 2qb+1
    for (int kb = 0; kb < nkb; kb++) {
        __syncthreads();   // prior-iter smem reads done (covers Q load too)
        const float* kbase = g_qkv + ((size_t)(b * S_ + kb * 64)) * QKVO + KOFF + kvh * 64;
        const float* vbase = g_qkv + ((size_t)(b * S_ + kb * 64)) * QKVO + VOFF + kvh * 64;
#pragma unroll
        for (int i = 0; i < 8; i++) {
            int e = tid + i * 128;
            int c = e >> 4, d4 = (e & 15) * 4;
            float4 kv = *(const float4*)(kbase + (size_t)c * QKVO + d4);
            float4 vv = *(const float4*)(vbase + (size_t)c * QKVO + d4);
            Kt[(d4 + 0) * 64 + c] = kv.x;
            Kt[(d4 + 1) * 64 + c] = kv.y;
            Kt[(d4 + 2) * 64 + c] = kv.z;
            Kt[(d4 + 3) * 64 + c] = kv.w;
            *(float4*)&Vs[c * 64 + d4] = vv;
        }
        __syncthreads();

        // S = Q K^T (scaled)
        float s[8][8];
#pragma unroll
        for (int i = 0; i < 8; i++)
#pragma unroll
            for (int j = 0; j < 8; j++) s[i][j] = 0.f;
#pragma unroll 4
        for (int d = 0; d < 64; d++) {
            float4 q0 = *(const float4*)&Qt[d * 128 + row0];
            float4 q1 = *(const float4*)&Qt[d * 128 + row0 + 4];
            float4 k0 = *(const float4*)&Kt[d * 64 + col0];
            float4 k1 = *(const float4*)&Kt[d * 64 + col0 + 4];
            float qr[8] = {q0.x, q0.y, q0.z, q0.w, q1.x, q1.y, q1.z, q1.w};
            float kr[8] = {k0.x, k0.y, k0.z, k0.w, k1.x, k1.y, k1.z, k1.w};
#pragma unroll
            for (int i = 0; i < 8; i++)
#pragma unroll
                for (int j = 0; j < 8; j++) s[i][j] += qr[i] * kr[j];
        }

        // causal mask (only tiles touching/above the diagonal)
        if (kb * 64 + 63 > qb * 128) {
#pragma unroll
            for (int i = 0; i < 8; i++) {
                int qr = qb * 128 + row0 + i;
#pragma unroll
                for (int j = 0; j < 8; j++)
                    if (kb * 64 + col0 + j > qr) s[i][j] = -1e30f;
            }
        }

        // online softmax per row (reduce over 8-lane tx groups)
#pragma unroll
        for (int i = 0; i < 8; i++) {
            float mt = s[i][0];
#pragma unroll
            for (int j = 1; j < 8; j++) mt = fmaxf(mt, s[i][j]);
#pragma unroll
            for (int off = 4; off > 0; off >>= 1)
                mt = fmaxf(mt, __shfl_xor_sync(0xffffffffu, mt, off));
            float mn = fmaxf(m_i[i], mt);
            float corr = __expf(m_i[i] - mn);
            float rs = 0.f;
#pragma unroll
            for (int j = 0; j < 8; j++) {
                float p = __expf(s[i][j] - mn);
                s[i][j] = p;
                rs += p;
            }
#pragma unroll
            for (int off = 4; off > 0; off >>= 1)
                rs += __shfl_xor_sync(0xffffffffu, rs, off);
            l_i[i] = l_i[i] * corr + rs;
            m_i[i] = mn;
#pragma unroll
            for (int j = 0; j < 8; j++) acc[i][j] *= corr;
        }

        // stage P transposed: Pt[c][r]
#pragma unroll
        for (int j = 0; j < 8; j++)
#pragma unroll
            for (int i = 0; i < 8; i++)
                Pt[(col0 + j) * 129 + row0 + i] = s[i][j];
        __syncthreads();

        // acc += P V
#pragma unroll 4
        for (int kk = 0; kk < 64; kk++) {
            float4 v0 = *(const float4*)&Vs[kk * 64 + col0];
            float4 v1 = *(const float4*)&Vs[kk * 64 + col0 + 4];
            float vr[8] = {v0.x, v0.y, v0.z, v0.w, v1.x, v1.y, v1.z, v1.w};
            float pv[8];
#pragma unroll
            for (int i = 0; i < 8; i++) pv[i] = Pt[kk * 129 + row0 + i];
#pragma unroll
            for (int i = 0; i < 8; i++)
#pragma unroll
                for (int j = 0; j < 8; j++) acc[i][j] += pv[i] * vr[j];
        }
    }

    float* obase = g_attn + ((size_t)(b * S_ + qb * 128)) * DIM_ + h * 64;
#pragma unroll
    for (int i = 0; i < 8; i++) {
        float inv = 1.f / l_i[i];
        float4 c0 = make_float4(acc[i][0] * inv, acc[i][1] * inv,
                                acc[i][2] * inv, acc[i][3] * inv);
        float4 c1 = make_float4(acc[i][4] * inv, acc[i][5] * inv,
                                acc[i][6] * inv, acc[i][7] * inv);
        float* orow = obase + (size_t)(row0 + i) * DIM_ + col0;
        *(float4*)orow = c0;
        *(float4*)(orow + 4) = c1;
    }
}

// ---------------------------------------------------------------------------
extern "C" void kernel_launch(void* const* d_in, const int* in_sizes, int n_in,
                              void* d_out, int out_size)
{
    const float* x     = (const float*)d_in[0];
    const float* wqkv  = (const float*)d_in[1];
    const float* wo    = (const float*)d_in[2];
    const float* q_g   = (const float*)d_in[3];
    const float* q_b   = (const float*)d_in[4];
    const float* k_g   = (const float*)d_in[5];
    const float* k_b   = (const float*)d_in[6];
    const float* fcos  = (const float*)d_in[7];
    const float* fsin  = (const float*)d_in[8];
    float* out = (float*)d_out;

    float* qkv_p = nullptr;
    float* attn_p = nullptr;
    cudaGetSymbolAddress((void**)&qkv_p, g_qkv);
    cudaGetSymbolAddress((void**)&attn_p, g_attn);

    const int M = B_ * S_;  // 4096

    // 1) QKV projection: x (M x 2048) * wqkv^T -> (M x 3072)
    {
        dim3 grid(QKVO / 128, M / 128);
        gemm_kernel<true><<<grid, 256>>>(x, wqkv, qkv_p, M, QKVO, DIM_);
    }

    // 2) LayerNorm + RoPE in-place
    {
        int total_warps = B_ * S_ * 40;
        lnrope_kernel<<<total_warps / 4, 128>>>(q_g, q_b, k_g, k_b, fcos, fsin);
    }

    // 3) Flash attention
    {
        cudaFuncSetAttribute(attn_kernel,
                             cudaFuncAttributeMaxDynamicSharedMemorySize, AT_SMEM);
        dim3 grid(S_ / 128, NH_, B_);
        attn_kernel<<<grid, 128, AT_SMEM>>>();
    }

    // 4) Output projection: attn (M x 2048) * wo (2048 x 2048)
    {
        dim3 grid(DIM_ / 128, M / 128);
        gemm_kernel<false><<<grid, 256>>>(attn_p, wo, out, M, DIM_, DIM_);
    }
}

// round 6
// speedup vs baseline: 5.8003x; 1.7719x over previous
#include <cuda_runtime.h>
#include <cuda_bf16.h>
#include <math.h>
#include <stdint.h>

// Problem constants
#define B_   2
#define S_   2048
#define DIM_ 2048
#define NH_  32
#define QKVO 3072          // (32 + 2*8) * 64
#define KOFF 2048
#define VOFF 2560
#define EPS_ 1e-5f
#define MTOT (B_ * S_)     // 4096

// Scratch (device globals — no allocation allowed)
__device__ float g_qkv[(size_t)B_ * S_ * QKVO];    // 50.3 MB
__device__ float g_attn[(size_t)B_ * S_ * DIM_];   // 33.5 MB
__device__ __nv_bfloat16 g_ahi[(size_t)MTOT * DIM_];   // 16.8 MB
__device__ __nv_bfloat16 g_alo[(size_t)MTOT * DIM_];   // 16.8 MB
__device__ __nv_bfloat16 g_bhi[(size_t)QKVO * DIM_];   // 12.6 MB
__device__ __nv_bfloat16 g_blo[(size_t)QKVO * DIM_];   // 12.6 MB

// ---------------------------------------------------------------------------
// PTX helpers (sm_103-safe: ldmatrix / mma.sync / cp.async only)
// ---------------------------------------------------------------------------
__device__ __forceinline__ uint32_t smem_u32(const void* p) {
    uint32_t a;
    asm("{ .reg .u64 t; cvta.to.shared.u64 t, %1; cvt.u32.u64 %0, t; }"
        : "=r"(a) : "l"(p));
    return a;
}
#define SWZ128(o) ((o) ^ (((o) >> 3) & 0x70))

__device__ __forceinline__ void ldm_x4(uint32_t* r, uint32_t addr) {
    asm volatile("ldmatrix.sync.aligned.m8n8.x4.shared.b16 {%0,%1,%2,%3}, [%4];"
                 : "=r"(r[0]), "=r"(r[1]), "=r"(r[2]), "=r"(r[3]) : "r"(addr));
}
__device__ __forceinline__ void mma_bf16(float* c, const uint32_t* a,
                                         uint32_t b0, uint32_t b1) {
    asm volatile(
        "mma.sync.aligned.m16n8k16.row.col.f32.bf16.bf16.f32 "
        "{%0,%1,%2,%3}, {%4,%5,%6,%7}, {%8,%9}, {%0,%1,%2,%3};"
        : "+f"(c[0]), "+f"(c[1]), "+f"(c[2]), "+f"(c[3])
        : "r"(a[0]), "r"(a[1]), "r"(a[2]), "r"(a[3]), "r"(b0), "r"(b1));
}
__device__ __forceinline__ void cpasync16(uint32_t s, const void* g) {
    asm volatile("cp.async.cg.shared.global [%0], [%1], 16;"
                 :: "r"(s), "l"(g) : "memory");
}
#define CP_COMMIT() asm volatile("cp.async.commit_group;" ::: "memory")
#define CP_WAIT1()  asm volatile("cp.async.wait_group 1;" ::: "memory")
#define CP_WAIT0()  asm volatile("cp.async.wait_group 0;" ::: "memory")

// ---------------------------------------------------------------------------
// fp32 -> bf16 hi/lo split (elementwise, float4-vectorized)
// ---------------------------------------------------------------------------
__global__ __launch_bounds__(256) void convert_split(
    const float* __restrict__ in, __nv_bfloat16* __restrict__ ohi,
    __nv_bfloat16* __restrict__ olo, int n4)
{
    int i = blockIdx.x * 256 + threadIdx.x;
    if (i >= n4) return;
    float4 v = ((const float4*)in)[i];
    __nv_bfloat16 h0 = __float2bfloat16(v.x), h1 = __float2bfloat16(v.y);
    __nv_bfloat16 h2 = __float2bfloat16(v.z), h3 = __float2bfloat16(v.w);
    __nv_bfloat16 l0 = __float2bfloat16(v.x - __bfloat162float(h0));
    __nv_bfloat16 l1 = __float2bfloat16(v.y - __bfloat162float(h1));
    __nv_bfloat16 l2 = __float2bfloat16(v.z - __bfloat162float(h2));
    __nv_bfloat16 l3 = __float2bfloat16(v.w - __bfloat162float(h3));
    __nv_bfloat162* H = (__nv_bfloat162*)(ohi + (size_t)i * 4);
    __nv_bfloat162* L = (__nv_bfloat162*)(olo + (size_t)i * 4);
    H[0] = __nv_bfloat162(h0, h1); H[1] = __nv_bfloat162(h2, h3);
    L[0] = __nv_bfloat162(l0, l1); L[1] = __nv_bfloat162(l2, l3);
}

// fp32 [R][C] -> transposed bf16 hi/lo [C][R]
__global__ __launch_bounds__(256) void convert_trans(
    const float* __restrict__ in, __nv_bfloat16* __restrict__ ohi,
    __nv_bfloat16* __restrict__ olo, int R, int C)
{
    __shared__ float t[32][33];
    int bx = blockIdx.x * 32, by = blockIdx.y * 32;
    int lx = threadIdx.x & 31, ly = threadIdx.x >> 5;
#pragma unroll
    for (int i = 0; i < 4; i++)
        t[ly + i * 8][lx] = in[(size_t)(by + ly + i * 8) * C + bx + lx];
    __syncthreads();
#pragma unroll
    for (int i = 0; i < 4; i++) {
        float v = t[lx][ly + i * 8];
        __nv_bfloat16 h = __float2bfloat16(v);
        __nv_bfloat16 l = __float2bfloat16(v - __bfloat162float(h));
        size_t o = (size_t)(bx + ly + i * 8) * R + by + lx;
        ohi[o] = h; olo[o] = l;
    }
}

// ---------------------------------------------------------------------------
// Warp-MMA GEMM: C[M,N] fp32 = A[M,K] * B[N,K]^T.  A,B bf16 hi/lo split,
// 3 products accumulated in fp32: Ah*Bh + Ah*Bl + Al*Bh.
// CTA tile 128x128, K-chunk 64, 256 thr (8 warps, warp tile 32x64),
// cp.async double-buffered smem with SW128 swizzle + ldmatrix.
// ---------------------------------------------------------------------------
#define STAGE 65536            // Ahi|Alo|Bhi|Blo, 16 KB each
#define GSMEM (2 * STAGE)      // 131072

__global__ __launch_bounds__(256) void gemm_mma(
    const __nv_bfloat16* __restrict__ Ahi, const __nv_bfloat16* __restrict__ Alo,
    const __nv_bfloat16* __restrict__ Bhi, const __nv_bfloat16* __restrict__ Blo,
    float* __restrict__ C, int N, int K)
{
    extern __shared__ char dyn[];
    const int tid  = threadIdx.x;
    const int wid  = tid >> 5;
    const int lane = tid & 31;
    const int m0 = (wid & 3) * 32;          // warp m offset in CTA tile
    const int n0 = (wid >> 2) * 64;         // warp n offset
    const int bm = blockIdx.y * 128;
    const int bn = blockIdx.x * 128;
    const uint32_t sbase = smem_u32(dyn);

    float acc[2][8][4];
#pragma unroll
    for (int mi = 0; mi < 2; mi++)
#pragma unroll
        for (int ni = 0; ni < 8; ni++)
#pragma unroll
            for (int q = 0; q < 4; q++) acc[mi][ni][q] = 0.f;

    // load mapping: u = tid + i*256 in [0,1024): row = u>>3, 16B-col = u&7
    const int nk = K >> 6;

    auto issue = [&](int ck) {
        const int buf = ck & 1;
        const int k0 = ck * 64;
        const uint32_t sb = sbase + buf * STAGE;
#pragma unroll
        for (int i = 0; i < 4; i++) {
            int u = tid + i * 256;
            int row = u >> 3, c16 = u & 7;
            uint32_t so = SWZ128((uint32_t)(row * 128 + c16 * 16));
            size_t ga = (size_t)(bm + row) * K + k0 + c16 * 8;
            size_t gb = (size_t)(bn + row) * K + k0 + c16 * 8;
            cpasync16(sb +         so, Ahi + ga);
            cpasync16(sb + 16384 + so, Alo + ga);
            cpasync16(sb + 32768 + so, Bhi + gb);
            cpasync16(sb + 49152 + so, Blo + gb);
        }
        CP_COMMIT();
    };

    issue(0);
    const int lrow = lane & 15;
    const int lcb  = (lane >> 4) * 16;      // byte offset for k-half

    for (int ck = 0; ck < nk; ck++) {
        if (ck + 1 < nk) { issue(ck + 1); CP_WAIT1(); }
        else             { CP_WAIT0(); }
        __syncthreads();
        const uint32_t sb = sbase + (ck & 1) * STAGE;

#pragma unroll
        for (int kk = 0; kk < 4; kk++) {
            uint32_t ah[2][4], al[2][4], bh[4][4], bl[4][4];
#pragma unroll
            for (int mi = 0; mi < 2; mi++) {
                uint32_t off = SWZ128((uint32_t)((m0 + mi * 16 + lrow) * 128 +
                                                 kk * 32 + lcb));
                ldm_x4(ah[mi], sb + off);
                ldm_x4(al[mi], sb + 16384 + off);
            }
#pragma unroll
            for (int nj = 0; nj < 4; nj++) {
                uint32_t off = SWZ128((uint32_t)((n0 + nj * 16 + lrow) * 128 +
                                                 kk * 32 + lcb));
                ldm_x4(bh[nj], sb + 32768 + off);
                ldm_x4(bl[nj], sb + 49152 + off);
            }
#pragma unroll
            for (int mi = 0; mi < 2; mi++)
#pragma unroll
                for (int ni = 0; ni < 8; ni++) {
                    const uint32_t* bf = bh[ni >> 1];
                    const uint32_t* bg = bl[ni >> 1];
                    uint32_t b0h = (ni & 1) ? bf[1] : bf[0];
                    uint32_t b1h = (ni & 1) ? bf[3] : bf[2];
                    uint32_t b0l = (ni & 1) ? bg[1] : bg[0];
                    uint32_t b1l = (ni & 1) ? bg[3] : bg[2];
                    mma_bf16(acc[mi][ni], ah[mi], b0h, b1h);
                    mma_bf16(acc[mi][ni], ah[mi], b0l, b1l);
                    mma_bf16(acc[mi][ni], al[mi], b0h, b1h);
                }
        }
        __syncthreads();
    }

    // epilogue: fragment layout m16n8 -> rows lane/4, lane/4+8; cols (lane%3)*2
#pragma unroll
    for (int mi = 0; mi < 2; mi++) {
        int r0 = bm + m0 + mi * 16 + (lane >> 2);
#pragma unroll
        for (int ni = 0; ni < 8; ni++) {
            int c = bn + n0 + ni * 8 + (lane & 3) * 2;
            *(float2*)&C[(size_t)r0 * N + c] =
                make_float2(acc[mi][ni][0], acc[mi][ni][1]);
            *(float2*)&C[(size_t)(r0 + 8) * N + c] =
                make_float2(acc[mi][ni][2], acc[mi][ni][3]);
        }
    }
}

// ---------------------------------------------------------------------------
// Fused LayerNorm + RoPE, in-place on g_qkv. One warp per (b,s,head).
// ---------------------------------------------------------------------------
__global__ __launch_bounds__(128) void lnrope_kernel(
    const float* __restrict__ qg, const float* __restrict__ qb,
    const float* __restrict__ kg, const float* __restrict__ kb,
    const float* __restrict__ fcos, const float* __restrict__ fsin)
{
    int gw = blockIdx.x * 4 + (threadIdx.x >> 5);
    int lane = threadIdx.x & 31;
    int h = gw % 40;
    int bs = gw / 40;
    int s = bs & (S_ - 1);

    float* ptr;
    const float* g;
    const float* be;
    size_t rowbase = (size_t)bs * QKVO;
    if (h < 32) { ptr = g_qkv + rowbase + h * 64;               g = qg; be = qb; }
    else        { ptr = g_qkv + rowbase + KOFF + (h - 32) * 64; g = kg; be = kb; }

    float2 v = reinterpret_cast<float2*>(ptr)[lane];
    float sum = v.x + v.y;
    float sq  = v.x * v.x + v.y * v.y;
#pragma unroll
    for (int off = 16; off > 0; off >>= 1) {
        sum += __shfl_xor_sync(0xffffffffu, sum, off);
        sq  += __shfl_xor_sync(0xffffffffu, sq,  off);
    }
    float mu   = sum * (1.f / 64.f);
    float var  = sq * (1.f / 64.f) - mu * mu;
    float rstd = rsqrtf(var + EPS_);

    float xr = (v.x - mu) * rstd * g[2 * lane]     + be[2 * lane];
    float xi = (v.y - mu) * rstd * g[2 * lane + 1] + be[2 * lane + 1];

    float c  = fcos[s * 32 + lane];
    float sn = fsin[s * 32 + lane];
    float2 o;
    o.x = xr * c - xi * sn;
    o.y = xr * sn + xi * c;
    reinterpret_cast<float2*>(ptr)[lane] = o;
}

// ---------------------------------------------------------------------------
// Flash attention (fp32 SIMT). 128 threads, Q tile 128, K tile 64, 8x8/thread.
// ---------------------------------------------------------------------------
#define AT_SMEM ((64 * 128 + 64 * 64 + 64 * 64 + 64 * 129) * 4)

__global__ __launch_bounds__(128) void attn_kernel()
{
    extern __shared__ float sm[];
    float* Qt = sm;                       // [64][128]
    float* Kt = sm + 64 * 128;            // [64][64]
    float* Vs = Kt + 64 * 64;             // [64][64]
    float* Pt = Vs + 64 * 64;             // [64][129]

    const int tid = threadIdx.x;
    const int ty = tid >> 3;
    const int tx = tid & 7;
    const int row0 = ty * 8;
    const int col0 = tx * 8;
    const int b = blockIdx.z, h = blockIdx.y;
    const int qb = (int)gridDim.x - 1 - (int)blockIdx.x;
    const int kvh = h >> 2;
    const float scale = 0.125f;

    const float* qbase = g_qkv + ((size_t)(b * S_ + qb * 128)) * QKVO + h * 64;
#pragma unroll
    for (int i = 0; i < 16; i++) {
        int e = tid + i * 128;
        int r = e >> 4, d4 = (e & 15) * 4;
        float4 v = *(const float4*)(qbase + (size_t)r * QKVO + d4);
        Qt[(d4 + 0) * 128 + r] = v.x * scale;
        Qt[(d4 + 1) * 128 + r] = v.y * scale;
        Qt[(d4 + 2) * 128 + r] = v.z * scale;
        Qt[(d4 + 3) * 128 + r] = v.w * scale;
    }

    float m_i[8], l_i[8], acc[8][8];
#pragma unroll
    for (int i = 0; i < 8; i++) { m_i[i] = -1e30f; l_i[i] = 0.f; }
#pragma unroll
    for (int i = 0; i < 8; i++)
#pragma unroll
        for (int j = 0; j < 8; j++) acc[i][j] = 0.f;

    const int nkb = 2 * qb + 2;
    for (int kb = 0; kb < nkb; kb++) {
        __syncthreads();
        const float* kbase = g_qkv + ((size_t)(b * S_ + kb * 64)) * QKVO + KOFF + kvh * 64;
        const float* vbase = g_qkv + ((size_t)(b * S_ + kb * 64)) * QKVO + VOFF + kvh * 64;
#pragma unroll
        for (int i = 0; i < 8; i++) {
            int e = tid + i * 128;
            int c = e >> 4, d4 = (e & 15) * 4;
            float4 kv = *(const float4*)(kbase + (size_t)c * QKVO + d4);
            float4 vv = *(const float4*)(vbase + (size_t)c * QKVO + d4);
            Kt[(d4 + 0) * 64 + c] = kv.x;
            Kt[(d4 + 1) * 64 + c] = kv.y;
            Kt[(d4 + 2) * 64 + c] = kv.z;
            Kt[(d4 + 3) * 64 + c] = kv.w;
            *(float4*)&Vs[c * 64 + d4] = vv;
        }
        __syncthreads();

        float s[8][8];
#pragma unroll
        for (int i = 0; i < 8; i++)
#pragma unroll
            for (int j = 0; j < 8; j++) s[i][j] = 0.f;
#pragma unroll 4
        for (int d = 0; d < 64; d++) {
            float4 q0 = *(const float4*)&Qt[d * 128 + row0];
            float4 q1 = *(const float4*)&Qt[d * 128 + row0 + 4];
            float4 k0 = *(const float4*)&Kt[d * 64 + col0];
            float4 k1 = *(const float4*)&Kt[d * 64 + col0 + 4];
            float qr[8] = {q0.x, q0.y, q0.z, q0.w, q1.x, q1.y, q1.z, q1.w};
            float kr[8] = {k0.x, k0.y, k0.z, k0.w, k1.x, k1.y, k1.z, k1.w};
#pragma unroll
            for (int i = 0; i < 8; i++)
#pragma unroll
                for (int j = 0; j < 8; j++) s[i][j] += qr[i] * kr[j];
        }

        if (kb * 64 + 63 > qb * 128) {
#pragma unroll
            for (int i = 0; i < 8; i++) {
                int qr = qb * 128 + row0 + i;
#pragma unroll
                for (int j = 0; j < 8; j++)
                    if (kb * 64 + col0 + j > qr) s[i][j] = -1e30f;
            }
        }

#pragma unroll
        for (int i = 0; i < 8; i++) {
            float mt = s[i][0];
#pragma unroll
            for (int j = 1; j < 8; j++) mt = fmaxf(mt, s[i][j]);
#pragma unroll
            for (int off = 4; off > 0; off >>= 1)
                mt = fmaxf(mt, __shfl_xor_sync(0xffffffffu, mt, off));
            float mn = fmaxf(m_i[i], mt);
            float corr = __expf(m_i[i] - mn);
            float rs = 0.f;
#pragma unroll
            for (int j = 0; j < 8; j++) {
                float p = __expf(s[i][j] - mn);
                s[i][j] = p;
                rs += p;
            }
#pragma unroll
            for (int off = 4; off > 0; off >>= 1)
                rs += __shfl_xor_sync(0xffffffffu, rs, off);
            l_i[i] = l_i[i] * corr + rs;
            m_i[i] = mn;
#pragma unroll
            for (int j = 0; j < 8; j++) acc[i][j] *= corr;
        }

#pragma unroll
        for (int j = 0; j < 8; j++)
#pragma unroll
            for (int i = 0; i < 8; i++)
                Pt[(col0 + j) * 129 + row0 + i] = s[i][j];
        __syncthreads();

#pragma unroll 4
        for (int kk = 0; kk < 64; kk++) {
            float4 v0 = *(const float4*)&Vs[kk * 64 + col0];
            float4 v1 = *(const float4*)&Vs[kk * 64 + col0 + 4];
            float vr[8] = {v0.x, v0.y, v0.z, v0.w, v1.x, v1.y, v1.z, v1.w};
            float pv[8];
#pragma unroll
            for (int i = 0; i < 8; i++) pv[i] = Pt[kk * 129 + row0 + i];
#pragma unroll
            for (int i = 0; i < 8; i++)
#pragma unroll
                for (int j = 0; j < 8; j++) acc[i][j] += pv[i] * vr[j];
        }
    }

    float* obase = g_attn + ((size_t)(b * S_ + qb * 128)) * DIM_ + h * 64;
#pragma unroll
    for (int i = 0; i < 8; i++) {
        float inv = 1.f / l_i[i];
        float4 c0 = make_float4(acc[i][0] * inv, acc[i][1] * inv,
                                acc[i][2] * inv, acc[i][3] * inv);
        float4 c1 = make_float4(acc[i][4] * inv, acc[i][5] * inv,
                                acc[i][6] * inv, acc[i][7] * inv);
        float* orow = obase + (size_t)(row0 + i) * DIM_ + col0;
        *(float4*)orow = c0;
        *(float4*)(orow + 4) = c1;
    }
}

// ---------------------------------------------------------------------------
extern "C" void kernel_launch(void* const* d_in, const int* in_sizes, int n_in,
                              void* d_out, int out_size)
{
    const float* x     = (const float*)d_in[0];
    const float* wqkv  = (const float*)d_in[1];
    const float* wo    = (const float*)d_in[2];
    const float* q_g   = (const float*)d_in[3];
    const float* q_b   = (const float*)d_in[4];
    const float* k_g   = (const float*)d_in[5];
    const float* k_b   = (const float*)d_in[6];
    const float* fcos  = (const float*)d_in[7];
    const float* fsin  = (const float*)d_in[8];
    float* out = (float*)d_out;

    float *qkv_p = nullptr, *attn_p = nullptr;
    __nv_bfloat16 *ahi, *alo, *bhi, *blo;
    cudaGetSymbolAddress((void**)&qkv_p, g_qkv);
    cudaGetSymbolAddress((void**)&attn_p, g_attn);
    cudaGetSymbolAddress((void**)&ahi, g_ahi);
    cudaGetSymbolAddress((void**)&alo, g_alo);
    cudaGetSymbolAddress((void**)&bhi, g_bhi);
    cudaGetSymbolAddress((void**)&blo, g_blo);

    cudaFuncSetAttribute(gemm_mma,
                         cudaFuncAttributeMaxDynamicSharedMemorySize, GSMEM);
    cudaFuncSetAttribute(attn_kernel,
                         cudaFuncAttributeMaxDynamicSharedMemorySize, AT_SMEM);

    // 1) split x and wqkv to bf16 hi/lo
    {
        int n4 = MTOT * DIM_ / 4;
        convert_split<<<(n4 + 255) / 256, 256>>>(x, ahi, alo, n4);
        int w4 = QKVO * DIM_ / 4;
        convert_split<<<(w4 + 255) / 256, 256>>>(wqkv, bhi, blo, w4);
    }

    // 2) QKV projection (tensor cores): qkv[4096][3072]
    {
        dim3 grid(QKVO / 128, MTOT / 128);
        gemm_mma<<<grid, 256, GSMEM>>>(ahi, alo, bhi, blo, qkv_p, QKVO, DIM_);
    }

    // 3) LayerNorm + RoPE in-place
    lnrope_kernel<<<B_ * S_ * 40 / 4, 128>>>(q_g, q_b, k_g, k_b, fcos, fsin);

    // 4) Flash attention (fp32 SIMT)
    {
        dim3 grid(S_ / 128, NH_, B_);
        attn_kernel<<<grid, 128, AT_SMEM>>>();
    }

    // 5) split attn output; transpose+split wo -> [d][f]
    {
        int n4 = MTOT * DIM_ / 4;
        convert_split<<<(n4 + 255) / 256, 256>>>(attn_p, ahi, alo, n4);
        dim3 tg(DIM_ / 32, DIM_ / 32);
        convert_trans<<<tg, 256>>>(wo, bhi, blo, DIM_, DIM_);
    }

    // 6) Output projection (tensor cores): out[4096][2048]
    {
        dim3 grid(DIM_ / 128, MTOT / 128);
        gemm_mma<<<grid, 256, GSMEM>>>(ahi, alo, bhi, blo, out, DIM_, DIM_);
    }
}

// round 7
// speedup vs baseline: 9.6886x; 1.6704x over previous
#include <cuda_runtime.h>
#include <cuda_bf16.h>
#include <math.h>
#include <stdint.h>

// Problem constants
#define B_   2
#define S_   2048
#define DIM_ 2048
#define NH_  32
#define NKVH 8
#define QKVO 3072          // (32 + 2*8) * 64
#define KOFF 2048
#define VOFF 2560
#define EPS_ 1e-5f
#define MTOT (B_ * S_)     // 4096

// Scratch (device globals — no allocation allowed)
__device__ float g_qkv[(size_t)B_ * S_ * QKVO];                  // 50.3 MB
__device__ __nv_bfloat16 g_ahi[(size_t)MTOT * DIM_];             // 16.8 MB
__device__ __nv_bfloat16 g_alo[(size_t)MTOT * DIM_];
__device__ __nv_bfloat16 g_bhi[(size_t)QKVO * DIM_];             // 12.6 MB
__device__ __nv_bfloat16 g_blo[(size_t)QKVO * DIM_];
// attention operand splits
__device__ __nv_bfloat16 g_qh[(size_t)B_ * NH_ * S_ * 64];       // 16.8 MB
__device__ __nv_bfloat16 g_ql[(size_t)B_ * NH_ * S_ * 64];
__device__ __nv_bfloat16 g_kh[(size_t)B_ * NKVH * S_ * 64];      // 4.2 MB
__device__ __nv_bfloat16 g_kl[(size_t)B_ * NKVH * S_ * 64];
__device__ __nv_bfloat16 g_vh[(size_t)B_ * NKVH * 64 * S_];      // [d][s]
__device__ __nv_bfloat16 g_vl[(size_t)B_ * NKVH * 64 * S_];

// ---------------------------------------------------------------------------
// PTX helpers (sm_103-safe)
// ---------------------------------------------------------------------------
__device__ __forceinline__ uint32_t smem_u32(const void* p) {
    uint32_t a;
    asm("{ .reg .u64 t; cvta.to.shared.u64 t, %1; cvt.u32.u64 %0, t; }"
        : "=r"(a) : "l"(p));
    return a;
}
#define SWZ128(o) ((o) ^ (((o) >> 3) & 0x70))

__device__ __forceinline__ void ldm_x4(uint32_t* r, uint32_t addr) {
    asm volatile("ldmatrix.sync.aligned.m8n8.x4.shared.b16 {%0,%1,%2,%3}, [%4];"
                 : "=r"(r[0]), "=r"(r[1]), "=r"(r[2]), "=r"(r[3]) : "r"(addr));
}
__device__ __forceinline__ void mma_bf16(float* c, const uint32_t* a,
                                         uint32_t b0, uint32_t b1) {
    asm volatile(
        "mma.sync.aligned.m16n8k16.row.col.f32.bf16.bf16.f32 "
        "{%0,%1,%2,%3}, {%4,%5,%6,%7}, {%8,%9}, {%0,%1,%2,%3};"
        : "+f"(c[0]), "+f"(c[1]), "+f"(c[2]), "+f"(c[3])
        : "r"(a[0]), "r"(a[1]), "r"(a[2]), "r"(a[3]), "r"(b0), "r"(b1));
}
__device__ __forceinline__ void cpasync16(uint32_t s, const void* g) {
    asm volatile("cp.async.cg.shared.global [%0], [%1], 16;"
                 :: "r"(s), "l"(g) : "memory");
}
#define CP_COMMIT() asm volatile("cp.async.commit_group;" ::: "memory")
#define CP_WAIT2()  asm volatile("cp.async.wait_group 2;" ::: "memory")
#define CP_WAIT1()  asm volatile("cp.async.wait_group 1;" ::: "memory")
#define CP_WAIT0()  asm volatile("cp.async.wait_group 0;" ::: "memory")

__device__ __forceinline__ void split2(float x, float y,
                                       uint32_t& hi, uint32_t& lo) {
    __nv_bfloat16 hx = __float2bfloat16(x), hy = __float2bfloat16(y);
    __nv_bfloat16 lx = __float2bfloat16(x - __bfloat162float(hx));
    __nv_bfloat16 ly = __float2bfloat16(y - __bfloat162float(hy));
    __nv_bfloat162 H(hx, hy), L(lx, ly);
    hi = *(uint32_t*)&H; lo = *(uint32_t*)&L;
}

// ---------------------------------------------------------------------------
// fp32 -> bf16 hi/lo split (elementwise)
// ---------------------------------------------------------------------------
__global__ __launch_bounds__(256) void convert_split(
    const float* __restrict__ in, __nv_bfloat16* __restrict__ ohi,
    __nv_bfloat16* __restrict__ olo, int n4)
{
    int i = blockIdx.x * 256 + threadIdx.x;
    if (i >= n4) return;
    float4 v = ((const float4*)in)[i];
    uint32_t h0, l0, h1, l1;
    split2(v.x, v.y, h0, l0);
    split2(v.z, v.w, h1, l1);
    uint32_t* H = (uint32_t*)(ohi + (size_t)i * 4);
    uint32_t* L = (uint32_t*)(olo + (size_t)i * 4);
    H[0] = h0; H[1] = h1; L[0] = l0; L[1] = l1;
}

// fp32 [R][C] -> transposed bf16 hi/lo [C][R]
__global__ __launch_bounds__(256) void convert_trans(
    const float* __restrict__ in, __nv_bfloat16* __restrict__ ohi,
    __nv_bfloat16* __restrict__ olo, int R, int C)
{
    __shared__ float t[32][33];
    int bx = blockIdx.x * 32, by = blockIdx.y * 32;
    int lx = threadIdx.x & 31, ly = threadIdx.x >> 5;
#pragma unroll
    for (int i = 0; i < 4; i++)
        t[ly + i * 8][lx] = in[(size_t)(by + ly + i * 8) * C + bx + lx];
    __syncthreads();
#pragma unroll
    for (int i = 0; i < 4; i++) {
        float v = t[lx][ly + i * 8];
        __nv_bfloat16 h = __float2bfloat16(v);
        __nv_bfloat16 l = __float2bfloat16(v - __bfloat162float(h));
        size_t o = (size_t)(bx + ly + i * 8) * R + by + lx;
        ohi[o] = h; olo[o] = l;
    }
}

// ---------------------------------------------------------------------------
// Warp-MMA GEMM (unchanged from round 6): C = A * B^T with hi/lo split.
// ---------------------------------------------------------------------------
#define STAGE 65536
#define GSMEM (2 * STAGE)

__global__ __launch_bounds__(256) void gemm_mma(
    const __nv_bfloat16* __restrict__ Ahi, const __nv_bfloat16* __restrict__ Alo,
    const __nv_bfloat16* __restrict__ Bhi, const __nv_bfloat16* __restrict__ Blo,
    float* __restrict__ C, int N, int K)
{
    extern __shared__ char dyn[];
    const int tid  = threadIdx.x;
    const int wid  = tid >> 5;
    const int lane = tid & 31;
    const int m0 = (wid & 3) * 32;
    const int n0 = (wid >> 2) * 64;
    const int bm = blockIdx.y * 128;
    const int bn = blockIdx.x * 128;
    const uint32_t sbase = smem_u32(dyn);

    float acc[2][8][4];
#pragma unroll
    for (int mi = 0; mi < 2; mi++)
#pragma unroll
        for (int ni = 0; ni < 8; ni++)
#pragma unroll
            for (int q = 0; q < 4; q++) acc[mi][ni][q] = 0.f;

    const int nk = K >> 6;

    auto issue = [&](int ck) {
        const int buf = ck & 1;
        const int k0 = ck * 64;
        const uint32_t sb = sbase + buf * STAGE;
#pragma unroll
        for (int i = 0; i < 4; i++) {
            int u = tid + i * 256;
            int row = u >> 3, c16 = u & 7;
            uint32_t so = SWZ128((uint32_t)(row * 128 + c16 * 16));
            size_t ga = (size_t)(bm + row) * K + k0 + c16 * 8;
            size_t gb = (size_t)(bn + row) * K + k0 + c16 * 8;
            cpasync16(sb +         so, Ahi + ga);
            cpasync16(sb + 16384 + so, Alo + ga);
            cpasync16(sb + 32768 + so, Bhi + gb);
            cpasync16(sb + 49152 + so, Blo + gb);
        }
        CP_COMMIT();
    };

    issue(0);
    const int lrow = lane & 15;
    const int lcb  = (lane >> 4) * 16;

    for (int ck = 0; ck < nk; ck++) {
        if (ck + 1 < nk) { issue(ck + 1); CP_WAIT1(); }
        else             { CP_WAIT0(); }
        __syncthreads();
        const uint32_t sb = sbase + (ck & 1) * STAGE;

#pragma unroll
        for (int kk = 0; kk < 4; kk++) {
            uint32_t ah[2][4], al[2][4], bh[4][4], bl[4][4];
#pragma unroll
            for (int mi = 0; mi < 2; mi++) {
                uint32_t off = SWZ128((uint32_t)((m0 + mi * 16 + lrow) * 128 +
                                                 kk * 32 + lcb));
                ldm_x4(ah[mi], sb + off);
                ldm_x4(al[mi], sb + 16384 + off);
            }
#pragma unroll
            for (int nj = 0; nj < 4; nj++) {
                uint32_t off = SWZ128((uint32_t)((n0 + nj * 16 + lrow) * 128 +
                                                 kk * 32 + lcb));
                ldm_x4(bh[nj], sb + 32768 + off);
                ldm_x4(bl[nj], sb + 49152 + off);
            }
#pragma unroll
            for (int mi = 0; mi < 2; mi++)
#pragma unroll
                for (int ni = 0; ni < 8; ni++) {
                    const uint32_t* bf = bh[ni >> 1];
                    const uint32_t* bg = bl[ni >> 1];
                    uint32_t b0h = (ni & 1) ? bf[1] : bf[0];
                    uint32_t b1h = (ni & 1) ? bf[3] : bf[2];
                    uint32_t b0l = (ni & 1) ? bg[1] : bg[0];
                    uint32_t b1l = (ni & 1) ? bg[3] : bg[2];
                    mma_bf16(acc[mi][ni], ah[mi], b0h, b1h);
                    mma_bf16(acc[mi][ni], ah[mi], b0l, b1l);
                    mma_bf16(acc[mi][ni], al[mi], b0h, b1h);
                }
        }
        __syncthreads();
    }

#pragma unroll
    for (int mi = 0; mi < 2; mi++) {
        int r0 = bm + m0 + mi * 16 + (lane >> 2);
#pragma unroll
        for (int ni = 0; ni < 8; ni++) {
            int c = bn + n0 + ni * 8 + (lane & 3) * 2;
            *(float2*)&C[(size_t)r0 * N + c] =
                make_float2(acc[mi][ni][0], acc[mi][ni][1]);
            *(float2*)&C[(size_t)(r0 + 8) * N + c] =
                make_float2(acc[mi][ni][2], acc[mi][ni][3]);
        }
    }
}

// ---------------------------------------------------------------------------
// Fused LayerNorm + RoPE; writes Q (pre-scaled 1/8) and K as bf16 hi/lo
// in head-major layouts for the attention kernel.
// ---------------------------------------------------------------------------
__global__ __launch_bounds__(128) void lnrope_kernel(
    const float* __restrict__ qg, const float* __restrict__ qbeta,
    const float* __restrict__ kg, const float* __restrict__ kbeta,
    const float* __restrict__ fcos, const float* __restrict__ fsin)
{
    int gw = blockIdx.x * 4 + (threadIdx.x >> 5);
    int lane = threadIdx.x & 31;
    int h = gw % 40;
    int bs = gw / 40;
    int s = bs & (S_ - 1);
    int b = bs >> 11;

    const float* ptr;
    const float* g;
    const float* be;
    float scl;
    __nv_bfloat16 *dh, *dl;
    size_t rowbase = (size_t)bs * QKVO;
    if (h < 32) {
        ptr = g_qkv + rowbase + h * 64; g = qg; be = qbeta; scl = 0.125f;
        size_t o = ((size_t)(b * NH_ + h) * S_ + s) * 64;
        dh = g_qh + o; dl = g_ql + o;
    } else {
        int kh = h - 32;
        ptr = g_qkv + rowbase + KOFF + kh * 64; g = kg; be = kbeta; scl = 1.f;
        size_t o = ((size_t)(b * NKVH + kh) * S_ + s) * 64;
        dh = g_kh + o; dl = g_kl + o;
    }

    float2 v = ((const float2*)ptr)[lane];
    float sum = v.x + v.y;
    float sq  = v.x * v.x + v.y * v.y;
#pragma unroll
    for (int off = 16; off > 0; off >>= 1) {
        sum += __shfl_xor_sync(0xffffffffu, sum, off);
        sq  += __shfl_xor_sync(0xffffffffu, sq,  off);
    }
    float mu   = sum * (1.f / 64.f);
    float var  = sq * (1.f / 64.f) - mu * mu;
    float rstd = rsqrtf(var + EPS_);

    float xr = (v.x - mu) * rstd * g[2 * lane]     + be[2 * lane];
    float xi = (v.y - mu) * rstd * g[2 * lane + 1] + be[2 * lane + 1];

    float c  = fcos[s * 32 + lane];
    float sn = fsin[s * 32 + lane];
    float ox = (xr * c - xi * sn) * scl;
    float oy = (xr * sn + xi * c) * scl;

    uint32_t hi, lo;
    split2(ox, oy, hi, lo);
    ((uint32_t*)dh)[lane] = hi;
    ((uint32_t*)dl)[lane] = lo;
}

// ---------------------------------------------------------------------------
// V: fp32 [b][s][kvh*64+d] -> bf16 hi/lo transposed [b*8+kvh][d][s]
// ---------------------------------------------------------------------------
__global__ __launch_bounds__(256) void vtrans_kernel()
{
    __shared__ float t[32][33];
    int s0 = blockIdx.x * 32;
    int d0 = blockIdx.y * 32;
    int bz = blockIdx.z;            // b*8 + kvh
    int b = bz >> 3, kvh = bz & 7;
    int lx = threadIdx.x & 31, ly = threadIdx.x >> 5;
#pragma unroll
    for (int i = 0; i < 4; i++)
        t[ly + i * 8][lx] =
            g_qkv[(size_t)(b * S_ + s0 + ly + i * 8) * QKVO + VOFF + kvh * 64 + d0 + lx];
    __syncthreads();
#pragma unroll
    for (int i = 0; i < 4; i++) {
        float v = t[lx][ly + i * 8];
        __nv_bfloat16 h = __float2bfloat16(v);
        __nv_bfloat16 l = __float2bfloat16(v - __bfloat162float(h));
        size_t o = ((size_t)bz * 64 + d0 + ly + i * 8) * S_ + s0 + lx;
        g_vh[o] = h; g_vl[o] = l;
    }
}

// ---------------------------------------------------------------------------
// Tensor-core flash attention. 256 thr / 8 warps, Q tile 128 (16 rows/warp),
// K tile 64, 3-stage cp.async ring. 3-product hi/lo split for QK^T and PV.
// Writes output directly as bf16 hi/lo splits into gemm2's A buffers.
// ---------------------------------------------------------------------------
#define ATT_STAGE 32768               // Kh|Kl|Vh|Vl, 8 KB each
#define ATT_SMEM (3 * ATT_STAGE + 32768)   // + Qh|Ql (16 KB each) = 128 KB

__global__ __launch_bounds__(256) void attn_mma()
{
    extern __shared__ char dyn[];
    const int tid = threadIdx.x, wid = tid >> 5, lane = tid & 31;
    const int b = blockIdx.z, h = blockIdx.y;
    const int qb = (int)gridDim.x - 1 - (int)blockIdx.x;   // heavy first
    const int kvh = h >> 2;
    const uint32_t sb = smem_u32(dyn);
    const uint32_t qsm = sb + 3 * ATT_STAGE;

    const __nv_bfloat16* Qh = g_qh + ((size_t)(b * NH_ + h) * S_ + qb * 128) * 64;
    const __nv_bfloat16* Ql = g_ql + ((size_t)(b * NH_ + h) * S_ + qb * 128) * 64;
    const __nv_bfloat16* Kh = g_kh + (size_t)(b * NKVH + kvh) * S_ * 64;
    const __nv_bfloat16* Kl = g_kl + (size_t)(b * NKVH + kvh) * S_ * 64;
    const __nv_bfloat16* Vh = g_vh + (size_t)(b * NKVH + kvh) * 64 * S_;
    const __nv_bfloat16* Vl = g_vl + (size_t)(b * NKVH + kvh) * 64 * S_;

    const int nkb = 2 * qb + 2;

    auto issueKV = [&](int kb) {
        uint32_t st = sb + (kb % 3) * ATT_STAGE;
        const __nv_bfloat16* kh = Kh + (size_t)kb * 64 * 64;
        const __nv_bfloat16* kl = Kl + (size_t)kb * 64 * 64;
        const __nv_bfloat16* vh = Vh + kb * 64;
        const __nv_bfloat16* vl = Vl + kb * 64;
#pragma unroll
        for (int i = 0; i < 2; i++) {
            int u = tid + i * 256;
            int row = u >> 3, c16 = u & 7;
            uint32_t so = SWZ128((uint32_t)(row * 128 + c16 * 16));
            cpasync16(st +         so, kh + row * 64 + c16 * 8);
            cpasync16(st +  8192 + so, kl + row * 64 + c16 * 8);
            cpasync16(st + 16384 + so, vh + (size_t)row * S_ + c16 * 8);
            cpasync16(st + 24576 + so, vl + (size_t)row * S_ + c16 * 8);
        }
        CP_COMMIT();
    };

    // Q tile loads (group 0, committed by issueKV(0))
#pragma unroll
    for (int i = 0; i < 4; i++) {
        int u = tid + i * 256;
        int row = u >> 3, c16 = u & 7;
        uint32_t so = SWZ128((uint32_t)(row * 128 + c16 * 16));
        cpasync16(qsm +         so, Qh + (size_t)row * 64 + c16 * 8);
        cpasync16(qsm + 16384 + so, Ql + (size_t)row * 64 + c16 * 8);
    }
    issueKV(0);
    if (nkb > 1) issueKV(1);

    const int lrow = lane & 15;
    const int lcb  = (lane >> 4) * 16;

    uint32_t qfh[4][4], qfl[4][4];
    float o[8][4];
#pragma unroll
    for (int j = 0; j < 8; j++)
#pragma unroll
        for (int c = 0; c < 4; c++) o[j][c] = 0.f;
    float m0 = -1e30f, m1 = -1e30f, l0 = 0.f, l1 = 0.f;

    for (int kb = 0; kb < nkb; kb++) {
        __syncthreads();                       // stage reuse guard
        if (kb + 2 < nkb) { issueKV(kb + 2); CP_WAIT2(); }
        else if (kb + 1 < nkb) { CP_WAIT1(); }
        else { CP_WAIT0(); }
        __syncthreads();                       // data visible to all

        if (kb == 0) {
#pragma unroll
            for (int kc = 0; kc < 4; kc++) {
                uint32_t off = SWZ128((uint32_t)((wid * 16 + lrow) * 128 +
                                                 kc * 32 + lcb));
                ldm_x4(qfh[kc], qsm + off);
                ldm_x4(qfl[kc], qsm + 16384 + off);
            }
        }

        const uint32_t st = sb + (kb % 3) * ATT_STAGE;
        const int wrow0 = qb * 128 + wid * 16;
        if (kb * 64 > wrow0 + 15) continue;    // fully masked for this warp

        // ---- S = Q K^T (3-product split) ----
        float sc[8][4];
#pragma unroll
        for (int j = 0; j < 8; j++)
#pragma unroll
            for (int c = 0; c < 4; c++) sc[j][c] = 0.f;
#pragma unroll
        for (int kc = 0; kc < 4; kc++) {
#pragma unroll
            for (int nj = 0; nj < 4; nj++) {
                uint32_t off = SWZ128((uint32_t)((nj * 16 + lrow) * 128 +
                                                 kc * 32 + lcb));
                uint32_t bh[4], bl[4];
                ldm_x4(bh, st + off);
                ldm_x4(bl, st + 8192 + off);
#pragma unroll
                for (int sub = 0; sub < 2; sub++) {
                    int ni = nj * 2 + sub;
                    mma_bf16(sc[ni], qfh[kc], bh[sub], bh[2 + sub]);
                    mma_bf16(sc[ni], qfh[kc], bl[sub], bl[2 + sub]);
                    mma_bf16(sc[ni], qfl[kc], bh[sub], bh[2 + sub]);
                }
            }
        }

        // ---- causal mask ----
        const int gr0 = wrow0 + (lane >> 2);
        if (kb * 64 + 63 > wrow0) {
#pragma unroll
            for (int j = 0; j < 8; j++) {
                int cb = kb * 64 + j * 8 + (lane & 3) * 2;
                if (cb     > gr0)     sc[j][0] = -1e30f;
                if (cb + 1 > gr0)     sc[j][1] = -1e30f;
                if (cb     > gr0 + 8) sc[j][2] = -1e30f;
                if (cb + 1 > gr0 + 8) sc[j][3] = -1e30f;
            }
        }

        // ---- online softmax (fp32, quad reductions) ----
        float mt0 = -1e30f, mt1 = -1e30f;
#pragma unroll
        for (int j = 0; j < 8; j++) {
            mt0 = fmaxf(mt0, fmaxf(sc[j][0], sc[j][1]));
            mt1 = fmaxf(mt1, fmaxf(sc[j][2], sc[j][3]));
        }
#pragma unroll
        for (int off = 1; off <= 2; off <<= 1) {
            mt0 = fmaxf(mt0, __shfl_xor_sync(0xffffffffu, mt0, off));
            mt1 = fmaxf(mt1, __shfl_xor_sync(0xffffffffu, mt1, off));
        }
        float mn0 = fmaxf(m0, mt0), mn1 = fmaxf(m1, mt1);
        float cr0 = __expf(m0 - mn0), cr1 = __expf(m1 - mn1);
        float rs0 = 0.f, rs1 = 0.f;
#pragma unroll
        for (int j = 0; j < 8; j++) {
            sc[j][0] = __expf(sc[j][0] - mn0);
            sc[j][1] = __expf(sc[j][1] - mn0);
            sc[j][2] = __expf(sc[j][2] - mn1);
            sc[j][3] = __expf(sc[j][3] - mn1);
            rs0 += sc[j][0] + sc[j][1];
            rs1 += sc[j][2] + sc[j][3];
        }
#pragma unroll
        for (int off = 1; off <= 2; off <<= 1) {
            rs0 += __shfl_xor_sync(0xffffffffu, rs0, off);
            rs1 += __shfl_xor_sync(0xffffffffu, rs1, off);
        }
        l0 = l0 * cr0 + rs0; l1 = l1 * cr1 + rs1;
        m0 = mn0; m1 = mn1;
#pragma unroll
        for (int j = 0; j < 8; j++) {
            o[j][0] *= cr0; o[j][1] *= cr0;
            o[j][2] *= cr1; o[j][3] *= cr1;
        }

        // ---- PV: split P to bf16 hi/lo A-frags, 3-product mma ----
#pragma unroll
        for (int t = 0; t < 4; t++) {
            uint32_t aph[4], apl[4];
            split2(sc[2 * t][0],     sc[2 * t][1],     aph[0], apl[0]);
            split2(sc[2 * t][2],     sc[2 * t][3],     aph[1], apl[1]);
            split2(sc[2 * t + 1][0], sc[2 * t + 1][1], aph[2], apl[2]);
            split2(sc[2 * t + 1][2], sc[2 * t + 1][3], aph[3], apl[3]);
#pragma unroll
            for (int nj = 0; nj < 4; nj++) {
                uint32_t off = SWZ128((uint32_t)((nj * 16 + lrow) * 128 +
                                                 t * 32 + lcb));
                uint32_t bh[4], bl[4];
                ldm_x4(bh, st + 16384 + off);
                ldm_x4(bl, st + 24576 + off);
#pragma unroll
                for (int sub = 0; sub < 2; sub++) {
                    int ni = nj * 2 + sub;
                    mma_bf16(o[ni], aph, bh[sub], bh[2 + sub]);
                    mma_bf16(o[ni], aph, bl[sub], bl[2 + sub]);
                    mma_bf16(o[ni], apl, bh[sub], bh[2 + sub]);
                }
            }
        }
    }

    // ---- epilogue: write bf16 hi/lo splits directly into gemm2 A ----
    float il0 = 1.f / l0, il1 = 1.f / l1;
    int r0 = qb * 128 + wid * 16 + (lane >> 2);
    size_t row0 = (size_t)(b * S_ + r0) * DIM_;
    size_t row1 = row0 + (size_t)8 * DIM_;
    int colbase = h * 64 + (lane & 3) * 2;
#pragma unroll
    for (int j = 0; j < 8; j++) {
        uint32_t h0, lo0, h1, lo1;
        split2(o[j][0] * il0, o[j][1] * il0, h0, lo0);
        split2(o[j][2] * il1, o[j][3] * il1, h1, lo1);
        int c = colbase + j * 8;
        *(uint32_t*)(g_ahi + row0 + c) = h0;
        *(uint32_t*)(g_alo + row0 + c) = lo0;
        *(uint32_t*)(g_ahi + row1 + c) = h1;
        *(uint32_t*)(g_alo + row1 + c) = lo1;
    }
}

// ---------------------------------------------------------------------------
extern "C" void kernel_launch(void* const* d_in, const int* in_sizes, int n_in,
                              void* d_out, int out_size)
{
    const float* x     = (const float*)d_in[0];
    const float* wqkv  = (const float*)d_in[1];
    const float* wo    = (const float*)d_in[2];
    const float* q_g   = (const float*)d_in[3];
    const float* q_b   = (const float*)d_in[4];
    const float* k_g   = (const float*)d_in[5];
    const float* k_b   = (const float*)d_in[6];
    const float* fcos  = (const float*)d_in[7];
    const float* fsin  = (const float*)d_in[8];
    float* out = (float*)d_out;

    float* qkv_p = nullptr;
    __nv_bfloat16 *ahi, *alo, *bhi, *blo;
    cudaGetSymbolAddress((void**)&qkv_p, g_qkv);
    cudaGetSymbolAddress((void**)&ahi, g_ahi);
    cudaGetSymbolAddress((void**)&alo, g_alo);
    cudaGetSymbolAddress((void**)&bhi, g_bhi);
    cudaGetSymbolAddress((void**)&blo, g_blo);

    cudaFuncSetAttribute(gemm_mma,
                         cudaFuncAttributeMaxDynamicSharedMemorySize, GSMEM);
    cudaFuncSetAttribute(attn_mma,
                         cudaFuncAttributeMaxDynamicSharedMemorySize, ATT_SMEM);

    // 1) split x and wqkv to bf16 hi/lo
    {
        int n4 = MTOT * DIM_ / 4;
        convert_split<<<(n4 + 255) / 256, 256>>>(x, ahi, alo, n4);
        int w4 = QKVO * DIM_ / 4;
        convert_split<<<(w4 + 255) / 256, 256>>>(wqkv, bhi, blo, w4);
    }

    // 2) QKV projection (tensor cores)
    {
        dim3 grid(QKVO / 128, MTOT / 128);
        gemm_mma<<<grid, 256, GSMEM>>>(ahi, alo, bhi, blo, qkv_p, QKVO, DIM_);
    }

    // 3) LayerNorm + RoPE -> Q/K bf16 splits; V transpose/split
    lnrope_kernel<<<B_ * S_ * 40 / 4, 128>>>(q_g, q_b, k_g, k_b, fcos, fsin);
    {
        dim3 vg(S_ / 32, 2, B_ * NKVH);
        vtrans_kernel<<<vg, 256>>>();
    }

    // 4) Tensor-core flash attention (writes gemm2 A splits directly)
    {
        dim3 grid(S_ / 128, NH_, B_);
        attn_mma<<<grid, 256, ATT_SMEM>>>();
    }

    // 5) transpose+split wo -> [d][f]
    {
        dim3 tg(DIM_ / 32, DIM_ / 32);
        convert_trans<<<tg, 256>>>(wo, bhi, blo, DIM_, DIM_);
    }

    // 6) Output projection (tensor cores)
    {
        dim3 grid(DIM_ / 128, MTOT / 128);
        gemm_mma<<<grid, 256, GSMEM>>>(ahi, alo, bhi, blo, out, DIM_, DIM_);
    }
}